// round 16
// baseline (speedup 1.0000x reference)
#include <cuda_runtime.h>

// ---------------------------------------------------------------------------
// Single-sequence (batch row 255) 2-layer LSTM.
// R14 skeleton (64 layer-1 CTAs x 8 units, 64 layer-2 CTAs x 8 units, 256
// threads; tagged u64 (tick,value) pairs; poll-IS-the-data-load; distributed
// staging into smem; batched warp0 publishes; B 3-phase with Wih2*h1
// overlapped under the h2 poll). Round 16:
//   * distributed gate activation: after the butterfly reduce every lane has
//     the row sums, so lanes 0..3 of each reducing warp activate their rows
//     in parallel (encode A / always B) -> warp0 tail = gather + cell + tanh
//   * double-pumped blocking polls (2 rotating samples per address, no clock
//     spins) on A's h1 staging and B's h2 finish poll
// ---------------------------------------------------------------------------

#define HT   512
#define NA   64     // layer-1 CTAs, 8 units each
#define NBC  64     // layer-2 CTAs, 8 units each
#define NBLK 128
#define NTHR 256
#define R1   16   // h1 ring depth (A->B skew covered by backpressure)
#define R2   4    // h2 ring depth (B-B skew <= 1)
#define RO   4    // o  ring depth

typedef unsigned long long u64;

__device__ __align__(16) u64 g_h1p[R1][HT];
__device__ __align__(16) u64 g_h2p[R2][HT];
__device__ __align__(16) u64 g_op[RO][NBC];
__device__ int g_prog[NBC * 32];      // B progress flags, 128B padded

__device__ __forceinline__ float sigf(float v)   { return 1.0f / (1.0f + __expf(-v)); }
__device__ __forceinline__ float tanhff(float v) { return 2.0f / (1.0f + __expf(-2.0f * v)) - 1.0f; }

__device__ __forceinline__ u64 ldp(const u64* p) {
    u64 v; asm volatile("ld.relaxed.gpu.global.b64 %0, [%1];" : "=l"(v) : "l"(p) : "memory"); return v;
}
__device__ __forceinline__ void stp(u64* p, u64 v) {
    asm volatile("st.relaxed.gpu.global.b64 [%0], %1;" :: "l"(p), "l"(v) : "memory");
}
__device__ __forceinline__ int ldacq(const int* p) {
    int v; asm volatile("ld.acquire.gpu.global.b32 %0, [%1];" : "=r"(v) : "l"(p) : "memory"); return v;
}
__device__ __forceinline__ void strel(int* p, int v) {
    asm volatile("st.release.gpu.global.b32 [%0], %1;" :: "l"(p), "r"(v) : "memory");
}
__device__ __forceinline__ u64 mkpair(float f, unsigned tag) {
    return ((u64)tag << 32) | (u64)__float_as_uint(f);
}
__device__ __forceinline__ float pval(u64 v) { return __uint_as_float((unsigned)v); }
__device__ __forceinline__ unsigned ptag(u64 v) { return (unsigned)(v >> 32); }

// packed fp32x2 fused multiply-add (Blackwell double-rate fp32 pipe)
__device__ __forceinline__ u64 fma2(u64 a, u64 b, u64 c) {
    u64 d;
    asm("fma.rn.f32x2 %0, %1, %2, %3;" : "=l"(d) : "l"(a), "l"(b), "l"(c));
    return d;
}
__device__ __forceinline__ float hsum2(u64 a) {
    return __uint_as_float((unsigned)a) + __uint_as_float((unsigned)(a >> 32));
}

// Dual-address double-pumped poll: 2 rotating samples per address in flight,
// plain dependent loads (no clock spins). Fast path: 4 loads, immediate hit.
#define POLL2X2(P0, P1, TAG, OUT0, OUT1)                                     \
{                                                                             \
    u64 _a0 = ldp(P0), _b0 = ldp(P0), _a1 = ldp(P1), _b1 = ldp(P1);           \
    bool _d0 = false, _d1 = false;                                            \
    for (;;) {                                                                \
        if (!_d0) {                                                           \
            if (ptag(_a0) == (TAG)) { OUT0 = _a0; _d0 = true; }               \
            else { u64 _n = ldp(P0); _a0 = _b0; _b0 = _n; }                   \
        }                                                                     \
        if (!_d1) {                                                           \
            if (ptag(_a1) == (TAG)) { OUT1 = _a1; _d1 = true; }               \
            else { u64 _n = ldp(P1); _a1 = _b1; _b1 = _n; }                   \
        }                                                                     \
        if (_d0 && _d1) break;                                                \
    }                                                                         \
}

__global__ void init_state_kernel() {
    int tid = threadIdx.x;
    for (int i = tid; i < R1 * HT;  i += NTHR) ((u64*)g_h1p)[i] = 0ull;  // tag 0, val 0
    for (int i = tid; i < R2 * HT;  i += NTHR) ((u64*)g_h2p)[i] = 0ull;
    for (int i = tid; i < RO * NBC; i += NTHR) ((u64*)g_op)[i]  = 0ull;
    for (int i = tid; i < NBC * 32; i += NTHR) g_prog[i] = 0;
}

__global__ void __launch_bounds__(NTHR, 1) lstm_distact_kernel(
    const float* __restrict__ input,
    const float* __restrict__ Wih1, const float* __restrict__ Whh1,
    const float* __restrict__ bih1, const float* __restrict__ bhh1,
    const float* __restrict__ Wih2, const float* __restrict__ Whh2,
    const float* __restrict__ bih2, const float* __restrict__ bhh2,
    const float* __restrict__ Wlin, const float* __restrict__ blin,
    float* __restrict__ out, int T, int pred_len, int Brows)
{
    __shared__ __align__(16) float sh1[HT];
    __shared__ __align__(16) float sh2[HT];
    __shared__ float sg[32];
    __shared__ float sb[32];
    __shared__ float swx[32];
    __shared__ float swlin[8];
    __shared__ float sxin[1024];

    const int tid  = threadIdx.x;
    const int wid  = tid >> 5;      // 8 warps; warp w owns local rows 4w..4w+3
    const int lane = tid & 31;
    const int total = T + pred_len - 1;

    if (blockIdx.x < NA) {
        // ===================== GROUP A : layer 1 (8 units) =====================
        const int bA = blockIdx.x * 8;
        // local row r (0..31) -> global R = (r>>3)*512 + bA + (r&7); gate = r>>3
        u64 wA2[4][8];
        #pragma unroll
        for (int rr = 0; rr < 4; ++rr) {
            int r = wid * 4 + rr;
            int R = ((r >> 3) << 9) + bA + (r & 7);
            const u64* Wr2 = (const u64*)(Whh1 + (size_t)R * HT);
            #pragma unroll
            for (int p = 0; p < 8; ++p) wA2[rr][p] = Wr2[lane + 32 * p];
        }
        if (tid < 32) {
            int r = tid;
            int R = ((r >> 3) << 9) + bA + (r & 7);
            sb[r]  = bih1[R] + bhh1[R];
            swx[r] = Wih1[R];
        }
        const float* xin = input + (size_t)(Brows - 1) * T;
        for (int i = tid; i < T && i < 1024; i += NTHR) sxin[i] = xin[i];
        const float blin0 = blin[0];
        float c1 = 0.f;   // warp0 lanes<8
        __syncthreads();

        for (int t = 0; t < total; ++t) {
            const unsigned need = (unsigned)t;
            const unsigned ng   = (unsigned)(t + 1);
            const bool enc = (t < T);

            // ---- stage h1 tag t (2 pairs/thread, double-pumped poll) ----
            {
                const u64* p0 = &g_h1p[t & (R1 - 1)][tid];
                const u64* p1 = p0 + 256;
                u64 v0, v1;
                POLL2X2(p0, p1, need, v0, v1);
                sh1[tid]       = pval(v0);
                sh1[tid + 256] = pval(v1);
            }
            __syncthreads();

            // ---- gate matvec: 4 rows x (K=512 as 8 f32x2); butterfly keeps
            //      sums in all lanes; lanes 0..3 activate their rows (encode) ----
            {
                u64 hv2[8];
                const u64* sp = (const u64*)sh1;
                #pragma unroll
                for (int p = 0; p < 8; ++p) hv2[p] = sp[lane + 32 * p];
                float sArr[4];
                #pragma unroll
                for (int rr = 0; rr < 4; ++rr) {
                    u64 acc = 0ull;
                    #pragma unroll
                    for (int p = 0; p < 8; ++p) acc = fma2(wA2[rr][p], hv2[p], acc);
                    float a = hsum2(acc);
                    #pragma unroll
                    for (int o = 16; o; o >>= 1) a += __shfl_xor_sync(0xffffffffu, a, o);
                    sArr[rr] = a;   // all lanes hold the row sum
                }
                float mine = sArr[0];
                mine = (lane == 1) ? sArr[1] : mine;
                mine = (lane == 2) ? sArr[2] : mine;
                mine = (lane == 3) ? sArr[3] : mine;
                if (lane < 4) {
                    int r = wid * 4 + lane;
                    if (enc) {
                        float v = mine + sb[r] + sxin[t] * swx[r];
                        sg[r] = ((r >> 3) == 2) ? tanhff(v) : sigf(v);
                    } else {
                        sg[r] = mine;   // raw; warp0 adds x term in decode
                    }
                }
            }
            __syncthreads();

            // ---- warp0: backpressure + (decode x) + cell update + publish ----
            if (wid == 0) {
                if ((t & 7) == 0 && t >= 16) {
                    int bpn = t - 8;
                    const int* pp0 = &g_prog[lane * 32];
                    const int* pp1 = &g_prog[(lane + 32) * 32];
                    for (;;) {
                        bool ok = (ldacq(pp0) >= bpn) && (ldacq(pp1) >= bpn);
                        if (__ballot_sync(0xffffffffu, ok) == 0xffffffffu) break;
                    }
                }
                float a;
                if (enc) {
                    a = sg[lane];   // already activated
                } else {
                    const u64* q0 = &g_op[t & (RO - 1)][lane];
                    const u64* q1 = q0 + 32;
                    u64 a0, a1;
                    POLL2X2(q0, q1, need, a0, a1);
                    float ov = pval(a0) + pval(a1);
                    #pragma unroll
                    for (int o = 16; o; o >>= 1) ov += __shfl_xor_sync(0xffffffffu, ov, o);
                    float x = ov + blin0;
                    if (blockIdx.x == 0 && lane == 0) out[t - T] = x;
                    float v = sg[lane] + sb[lane] + x * swx[lane];
                    a = ((lane >> 3) == 2) ? tanhff(v) : sigf(v);
                }
                int u = lane & 7;
                float i_ = __shfl_sync(0xffffffffu, a, u);
                float f_ = __shfl_sync(0xffffffffu, a, u + 8);
                float g_ = __shfl_sync(0xffffffffu, a, u + 16);
                float o_ = __shfl_sync(0xffffffffu, a, u + 24);
                if (lane < 8) {
                    c1 = f_ * c1 + i_ * g_;
                    float hh = o_ * tanhff(c1);
                    stp(&g_h1p[(t + 1) & (R1 - 1)][bA + lane], mkpair(hh, ng));
                }
            }
        }

        // ---- epilogue: o tag total -> out[pred_len-1] ----
        if (blockIdx.x == 0 && wid == 0) {
            const unsigned nf = (unsigned)total;
            const u64* q0 = &g_op[total & (RO - 1)][lane];
            const u64* q1 = q0 + 32;
            u64 a0, a1;
            POLL2X2(q0, q1, nf, a0, a1);
            float ov = pval(a0) + pval(a1);
            #pragma unroll
            for (int o = 16; o; o >>= 1) ov += __shfl_xor_sync(0xffffffffu, ov, o);
            if (lane == 0) out[pred_len - 1] = ov + blin0;
        }
    } else {
        // ===================== GROUP B : layer 2 (8 units) =====================
        const int jB = blockIdx.x - NA;
        const int bB = jB * 8;
        u64 wB2[4][16];  // 4 rows x 16 f32x2 pairs (K=1024: [Wih2 | Whh2])
        #pragma unroll
        for (int rr = 0; rr < 4; ++rr) {
            int r = wid * 4 + rr;
            int R = ((r >> 3) << 9) + bB + (r & 7);
            const u64* Wi2 = (const u64*)(Wih2 + (size_t)R * HT);
            const u64* Wh2 = (const u64*)(Whh2 + (size_t)R * HT);
            #pragma unroll
            for (int p = 0; p < 8; ++p) {
                wB2[rr][p]     = Wi2[lane + 32 * p];
                wB2[rr][8 + p] = Wh2[lane + 32 * p];
            }
        }
        if (tid < 32) {
            int r = tid;
            int R = ((r >> 3) << 9) + bB + (r & 7);
            sb[r] = bih2[R] + bhh2[R];
        }
        if (tid < 8) swlin[tid] = Wlin[bB + tid];
        float c2 = 0.f;   // warp0 lanes<8
        __syncthreads();

        for (int k = 0; k < total; ++k) {
            const unsigned n1 = (unsigned)(k + 1);   // h1 tag needed / produced tag
            const unsigned n2 = (unsigned)k;         // h2 tag needed

            // ---- phase 1: stage h1 tag k+1 (early: A runs ahead) ----
            {
                const u64* p0 = &g_h1p[(k + 1) & (R1 - 1)][tid];
                const u64* p1 = p0 + 256;
                u64 v0, v1; bool o0 = false, o1 = false;
                do {
                    if (!o0) { v0 = ldp(p0); o0 = (ptag(v0) == n1); }
                    if (!o1) { v1 = ldp(p1); o1 = (ptag(v1) == n1); }
                } while (!(o0 && o1));
                sh1[tid]       = pval(v0);
                sh1[tid + 256] = pval(v1);
            }
            __syncthreads();
            if (tid == 0) strel(&g_prog[jB * 32], k);   // consumed h1 slot tag k+1

            // ---- phase 2: issue h2 samples (2 per address), overlap Wih2*h1 ----
            const u64* q0 = &g_h2p[k & (R2 - 1)][tid];
            const u64* q1 = q0 + 256;
            u64 w0a = ldp(q0), w0b = ldp(q0);
            u64 w1a = ldp(q1), w1b = ldp(q1);

            u64 acc[4] = {0ull, 0ull, 0ull, 0ull};
            {
                u64 hv[8];
                const u64* s1 = (const u64*)sh1;
                #pragma unroll
                for (int p = 0; p < 8; ++p) hv[p] = s1[lane + 32 * p];
                #pragma unroll
                for (int rr = 0; rr < 4; ++rr)
                    #pragma unroll
                    for (int p = 0; p < 8; ++p) acc[rr] = fma2(wB2[rr][p], hv[p], acc[rr]);
            }
            // finish h2 poll (double-pumped rotation)
            {
                u64 w0, w1; bool d0 = false, d1 = false;
                for (;;) {
                    if (!d0) {
                        if (ptag(w0a) == n2) { w0 = w0a; d0 = true; }
                        else { u64 n = ldp(q0); w0a = w0b; w0b = n; }
                    }
                    if (!d1) {
                        if (ptag(w1a) == n2) { w1 = w1a; d1 = true; }
                        else { u64 n = ldp(q1); w1a = w1b; w1b = n; }
                    }
                    if (d0 && d1) break;
                }
                sh2[tid]       = pval(w0);
                sh2[tid + 256] = pval(w1);
            }
            __syncthreads();

            // ---- phase 3: Whh2*h2 half + reduce + distributed activation ----
            {
                u64 hv[8];
                const u64* s2 = (const u64*)sh2;
                #pragma unroll
                for (int p = 0; p < 8; ++p) hv[p] = s2[lane + 32 * p];
                float sArr[4];
                #pragma unroll
                for (int rr = 0; rr < 4; ++rr) {
                    #pragma unroll
                    for (int p = 0; p < 8; ++p) acc[rr] = fma2(wB2[rr][8 + p], hv[p], acc[rr]);
                    float a = hsum2(acc[rr]);
                    #pragma unroll
                    for (int o = 16; o; o >>= 1) a += __shfl_xor_sync(0xffffffffu, a, o);
                    sArr[rr] = a;
                }
                float mine = sArr[0];
                mine = (lane == 1) ? sArr[1] : mine;
                mine = (lane == 2) ? sArr[2] : mine;
                mine = (lane == 3) ? sArr[3] : mine;
                if (lane < 4) {
                    int r = wid * 4 + lane;
                    float v = mine + sb[r];
                    sg[r] = ((r >> 3) == 2) ? tanhff(v) : sigf(v);
                }
            }
            __syncthreads();

            // ---- phase 4: warp0 cell update + batched publish (h2 + o) ----
            if (wid == 0) {
                float a = sg[lane];   // activated gate value for row=lane
                int u = lane & 7;
                float i_ = __shfl_sync(0xffffffffu, a, u);
                float f_ = __shfl_sync(0xffffffffu, a, u + 8);
                float g_ = __shfl_sync(0xffffffffu, a, u + 16);
                float o_ = __shfl_sync(0xffffffffu, a, u + 24);
                float p = 0.f;
                if (lane < 8) {
                    c2 = f_ * c2 + i_ * g_;
                    float hh = o_ * tanhff(c2);
                    stp(&g_h2p[(k + 1) & (R2 - 1)][bB + lane], mkpair(hh, n1));
                    p = swlin[lane] * hh;
                }
                if (k >= T - 1) {
                    p += __shfl_xor_sync(0xffffffffu, p, 4);
                    p += __shfl_xor_sync(0xffffffffu, p, 2);
                    p += __shfl_xor_sync(0xffffffffu, p, 1);
                    if (lane == 0)
                        stp(&g_op[(k + 1) & (RO - 1)][jB], mkpair(p, n1));
                }
            }
        }
    }
}

extern "C" void kernel_launch(void* const* d_in, const int* in_sizes, int n_in,
                              void* d_out, int out_size) {
    int off = (n_in >= 12 && in_sizes[1] == 1) ? 2 : 1;

    const float* input = (const float*)d_in[0];
    const float* Wih1  = (const float*)d_in[off + 0];
    const float* Whh1  = (const float*)d_in[off + 1];
    const float* bih1  = (const float*)d_in[off + 2];
    const float* bhh1  = (const float*)d_in[off + 3];
    const float* Wih2  = (const float*)d_in[off + 4];
    const float* Whh2  = (const float*)d_in[off + 5];
    const float* bih2  = (const float*)d_in[off + 6];
    const float* bhh2  = (const float*)d_in[off + 7];
    const float* Wlin  = (const float*)d_in[off + 8];
    const float* blin  = (const float*)d_in[off + 9];

    const int B = 256;
    const int T = in_sizes[0] / B;
    const int pred_len = out_size;

    init_state_kernel<<<1, NTHR>>>();
    lstm_distact_kernel<<<NBLK, NTHR>>>(
        input, Wih1, Whh1, bih1, bhh1, Wih2, Whh2, bih2, bhh2, Wlin, blin,
        (float*)d_out, T, pred_len, B);
}

// round 17
// speedup vs baseline: 1.1606x; 1.1606x over previous
#include <cuda_runtime.h>

// ---------------------------------------------------------------------------
// Single-sequence (batch row 255) 2-layer LSTM.
// R14 skeleton verbatim (64 layer-1 CTAs x 8 units, 64 layer-2 CTAs x 8
// units, 256 threads; tagged u64 (tick,value) pairs; plain DEPENDENT polls
// (poll IS the data load, self-throttling); distributed staging into smem;
// batched warp0 publishes; B 3-phase with Wih2*h1 overlapped under the h2
// poll). Round 17 delta: distributed gate activation — after the butterfly
// reduce every lane holds the row sums, so lanes 0..3 of each reducing warp
// activate their rows in parallel; warp0's serial tail shrinks to
// gather + cell update + tanh + publish.
// ---------------------------------------------------------------------------

#define HT   512
#define NA   64     // layer-1 CTAs, 8 units each
#define NBC  64     // layer-2 CTAs, 8 units each
#define NBLK 128
#define NTHR 256
#define R1   16   // h1 ring depth (A->B skew covered by backpressure)
#define R2   4    // h2 ring depth (B-B skew <= 1)
#define RO   4    // o  ring depth

typedef unsigned long long u64;

__device__ __align__(16) u64 g_h1p[R1][HT];
__device__ __align__(16) u64 g_h2p[R2][HT];
__device__ __align__(16) u64 g_op[RO][NBC];
__device__ int g_prog[NBC * 32];      // B progress flags, 128B padded

__device__ __forceinline__ float sigf(float v)   { return 1.0f / (1.0f + __expf(-v)); }
__device__ __forceinline__ float tanhff(float v) { return 2.0f / (1.0f + __expf(-2.0f * v)) - 1.0f; }

__device__ __forceinline__ u64 ldp(const u64* p) {
    u64 v; asm volatile("ld.relaxed.gpu.global.b64 %0, [%1];" : "=l"(v) : "l"(p) : "memory"); return v;
}
__device__ __forceinline__ void stp(u64* p, u64 v) {
    asm volatile("st.relaxed.gpu.global.b64 [%0], %1;" :: "l"(p), "l"(v) : "memory");
}
__device__ __forceinline__ int ldacq(const int* p) {
    int v; asm volatile("ld.acquire.gpu.global.b32 %0, [%1];" : "=r"(v) : "l"(p) : "memory"); return v;
}
__device__ __forceinline__ void strel(int* p, int v) {
    asm volatile("st.release.gpu.global.b32 [%0], %1;" :: "l"(p), "r"(v) : "memory");
}
__device__ __forceinline__ u64 mkpair(float f, unsigned tag) {
    return ((u64)tag << 32) | (u64)__float_as_uint(f);
}
__device__ __forceinline__ float pval(u64 v) { return __uint_as_float((unsigned)v); }
__device__ __forceinline__ unsigned ptag(u64 v) { return (unsigned)(v >> 32); }

// packed fp32x2 fused multiply-add (Blackwell double-rate fp32 pipe)
__device__ __forceinline__ u64 fma2(u64 a, u64 b, u64 c) {
    u64 d;
    asm("fma.rn.f32x2 %0, %1, %2, %3;" : "=l"(d) : "l"(a), "l"(b), "l"(c));
    return d;
}
__device__ __forceinline__ float hsum2(u64 a) {
    return __uint_as_float((unsigned)a) + __uint_as_float((unsigned)(a >> 32));
}

__global__ void init_state_kernel() {
    int tid = threadIdx.x;
    for (int i = tid; i < R1 * HT;  i += NTHR) ((u64*)g_h1p)[i] = 0ull;  // tag 0, val 0
    for (int i = tid; i < R2 * HT;  i += NTHR) ((u64*)g_h2p)[i] = 0ull;
    for (int i = tid; i < RO * NBC; i += NTHR) ((u64*)g_op)[i]  = 0ull;
    for (int i = tid; i < NBC * 32; i += NTHR) g_prog[i] = 0;
}

__global__ void __launch_bounds__(NTHR, 1) lstm_da2_kernel(
    const float* __restrict__ input,
    const float* __restrict__ Wih1, const float* __restrict__ Whh1,
    const float* __restrict__ bih1, const float* __restrict__ bhh1,
    const float* __restrict__ Wih2, const float* __restrict__ Whh2,
    const float* __restrict__ bih2, const float* __restrict__ bhh2,
    const float* __restrict__ Wlin, const float* __restrict__ blin,
    float* __restrict__ out, int T, int pred_len, int Brows)
{
    __shared__ __align__(16) float sh1[HT];
    __shared__ __align__(16) float sh2[HT];
    __shared__ float sg[32];
    __shared__ float sb[32];
    __shared__ float swx[32];
    __shared__ float swlin[8];
    __shared__ float sxin[1024];

    const int tid  = threadIdx.x;
    const int wid  = tid >> 5;      // 8 warps; warp w owns local rows 4w..4w+3
    const int lane = tid & 31;
    const int total = T + pred_len - 1;

    if (blockIdx.x < NA) {
        // ===================== GROUP A : layer 1 (8 units) =====================
        const int bA = blockIdx.x * 8;
        // local row r (0..31) -> global R = (r>>3)*512 + bA + (r&7); gate = r>>3
        u64 wA2[4][8];
        #pragma unroll
        for (int rr = 0; rr < 4; ++rr) {
            int r = wid * 4 + rr;
            int R = ((r >> 3) << 9) + bA + (r & 7);
            const u64* Wr2 = (const u64*)(Whh1 + (size_t)R * HT);
            #pragma unroll
            for (int p = 0; p < 8; ++p) wA2[rr][p] = Wr2[lane + 32 * p];
        }
        if (tid < 32) {
            int r = tid;
            int R = ((r >> 3) << 9) + bA + (r & 7);
            sb[r]  = bih1[R] + bhh1[R];
            swx[r] = Wih1[R];
        }
        const float* xin = input + (size_t)(Brows - 1) * T;
        for (int i = tid; i < T && i < 1024; i += NTHR) sxin[i] = xin[i];
        const float blin0 = blin[0];
        float c1 = 0.f;   // warp0 lanes<8
        __syncthreads();

        for (int t = 0; t < total; ++t) {
            const unsigned need = (unsigned)t;
            const unsigned ng   = (unsigned)(t + 1);
            const bool enc = (t < T);

            // ---- stage h1 tag t (2 pairs/thread, dependent poll) ----
            {
                const u64* p0 = &g_h1p[t & (R1 - 1)][tid];
                const u64* p1 = p0 + 256;
                u64 v0, v1; bool o0 = false, o1 = false;
                do {
                    if (!o0) { v0 = ldp(p0); o0 = (ptag(v0) == need); }
                    if (!o1) { v1 = ldp(p1); o1 = (ptag(v1) == need); }
                } while (!(o0 && o1));
                sh1[tid]       = pval(v0);
                sh1[tid + 256] = pval(v1);
            }
            __syncthreads();

            // ---- gate matvec: 4 rows x (K=512 as 8 f32x2); butterfly keeps
            //      sums in all lanes; lanes 0..3 activate their rows (encode) ----
            {
                u64 hv2[8];
                const u64* sp = (const u64*)sh1;
                #pragma unroll
                for (int p = 0; p < 8; ++p) hv2[p] = sp[lane + 32 * p];
                float sArr[4];
                #pragma unroll
                for (int rr = 0; rr < 4; ++rr) {
                    u64 acc = 0ull;
                    #pragma unroll
                    for (int p = 0; p < 8; ++p) acc = fma2(wA2[rr][p], hv2[p], acc);
                    float a = hsum2(acc);
                    #pragma unroll
                    for (int o = 16; o; o >>= 1) a += __shfl_xor_sync(0xffffffffu, a, o);
                    sArr[rr] = a;   // all lanes hold the row sum
                }
                float mine = sArr[0];
                mine = (lane == 1) ? sArr[1] : mine;
                mine = (lane == 2) ? sArr[2] : mine;
                mine = (lane == 3) ? sArr[3] : mine;
                if (lane < 4) {
                    int r = wid * 4 + lane;
                    if (enc) {
                        float v = mine + sb[r] + sxin[t] * swx[r];
                        sg[r] = ((r >> 3) == 2) ? tanhff(v) : sigf(v);
                    } else {
                        sg[r] = mine;   // raw; warp0 folds x in decode
                    }
                }
            }
            __syncthreads();

            // ---- warp0: backpressure + (decode x) + cell update + publish ----
            if (wid == 0) {
                if ((t & 7) == 0 && t >= 16) {
                    int bpn = t - 8;
                    const int* pp0 = &g_prog[lane * 32];
                    const int* pp1 = &g_prog[(lane + 32) * 32];
                    for (;;) {
                        bool ok = (ldacq(pp0) >= bpn) && (ldacq(pp1) >= bpn);
                        if (__ballot_sync(0xffffffffu, ok) == 0xffffffffu) break;
                    }
                }
                float a;
                if (enc) {
                    a = sg[lane];   // already activated
                } else {
                    const u64* q0 = &g_op[t & (RO - 1)][lane];
                    const u64* q1 = q0 + 32;
                    u64 a0, a1; bool d0 = false, d1 = false;
                    do {
                        if (!d0) { a0 = ldp(q0); d0 = (ptag(a0) == need); }
                        if (!d1) { a1 = ldp(q1); d1 = (ptag(a1) == need); }
                    } while (!(d0 && d1));
                    float ov = pval(a0) + pval(a1);
                    #pragma unroll
                    for (int o = 16; o; o >>= 1) ov += __shfl_xor_sync(0xffffffffu, ov, o);
                    float x = ov + blin0;
                    if (blockIdx.x == 0 && lane == 0) out[t - T] = x;
                    float v = sg[lane] + sb[lane] + x * swx[lane];
                    a = ((lane >> 3) == 2) ? tanhff(v) : sigf(v);
                }
                int u = lane & 7;
                float i_ = __shfl_sync(0xffffffffu, a, u);
                float f_ = __shfl_sync(0xffffffffu, a, u + 8);
                float g_ = __shfl_sync(0xffffffffu, a, u + 16);
                float o_ = __shfl_sync(0xffffffffu, a, u + 24);
                if (lane < 8) {
                    c1 = f_ * c1 + i_ * g_;
                    float hh = o_ * tanhff(c1);
                    stp(&g_h1p[(t + 1) & (R1 - 1)][bA + lane], mkpair(hh, ng));
                }
            }
        }

        // ---- epilogue: o tag total -> out[pred_len-1] ----
        if (blockIdx.x == 0 && wid == 0) {
            const unsigned nf = (unsigned)total;
            const u64* q0 = &g_op[total & (RO - 1)][lane];
            const u64* q1 = q0 + 32;
            u64 a0, a1; bool d0 = false, d1 = false;
            do {
                if (!d0) { a0 = ldp(q0); d0 = (ptag(a0) == nf); }
                if (!d1) { a1 = ldp(q1); d1 = (ptag(a1) == nf); }
            } while (!(d0 && d1));
            float ov = pval(a0) + pval(a1);
            #pragma unroll
            for (int o = 16; o; o >>= 1) ov += __shfl_xor_sync(0xffffffffu, ov, o);
            if (lane == 0) out[pred_len - 1] = ov + blin0;
        }
    } else {
        // ===================== GROUP B : layer 2 (8 units) =====================
        const int jB = blockIdx.x - NA;
        const int bB = jB * 8;
        u64 wB2[4][16];  // 4 rows x 16 f32x2 pairs (K=1024: [Wih2 | Whh2])
        #pragma unroll
        for (int rr = 0; rr < 4; ++rr) {
            int r = wid * 4 + rr;
            int R = ((r >> 3) << 9) + bB + (r & 7);
            const u64* Wi2 = (const u64*)(Wih2 + (size_t)R * HT);
            const u64* Wh2 = (const u64*)(Whh2 + (size_t)R * HT);
            #pragma unroll
            for (int p = 0; p < 8; ++p) {
                wB2[rr][p]     = Wi2[lane + 32 * p];
                wB2[rr][8 + p] = Wh2[lane + 32 * p];
            }
        }
        if (tid < 32) {
            int r = tid;
            int R = ((r >> 3) << 9) + bB + (r & 7);
            sb[r] = bih2[R] + bhh2[R];
        }
        if (tid < 8) swlin[tid] = Wlin[bB + tid];
        float c2 = 0.f;   // warp0 lanes<8
        __syncthreads();

        for (int k = 0; k < total; ++k) {
            const unsigned n1 = (unsigned)(k + 1);   // h1 tag needed / produced tag
            const unsigned n2 = (unsigned)k;         // h2 tag needed

            // ---- phase 1: stage h1 tag k+1 (early: A runs ahead) ----
            {
                const u64* p0 = &g_h1p[(k + 1) & (R1 - 1)][tid];
                const u64* p1 = p0 + 256;
                u64 v0, v1; bool o0 = false, o1 = false;
                do {
                    if (!o0) { v0 = ldp(p0); o0 = (ptag(v0) == n1); }
                    if (!o1) { v1 = ldp(p1); o1 = (ptag(v1) == n1); }
                } while (!(o0 && o1));
                sh1[tid]       = pval(v0);
                sh1[tid + 256] = pval(v1);
            }
            __syncthreads();
            if (tid == 0) strel(&g_prog[jB * 32], k);   // consumed h1 slot tag k+1

            // ---- phase 2: issue first h2 samples, overlap Wih2*h1 half ----
            const u64* q0 = &g_h2p[k & (R2 - 1)][tid];
            const u64* q1 = q0 + 256;
            u64 w0 = ldp(q0);
            u64 w1 = ldp(q1);
            bool d0 = (ptag(w0) == n2);
            bool d1 = (ptag(w1) == n2);

            u64 acc[4] = {0ull, 0ull, 0ull, 0ull};
            {
                u64 hv[8];
                const u64* s1 = (const u64*)sh1;
                #pragma unroll
                for (int p = 0; p < 8; ++p) hv[p] = s1[lane + 32 * p];
                #pragma unroll
                for (int rr = 0; rr < 4; ++rr)
                    #pragma unroll
                    for (int p = 0; p < 8; ++p) acc[rr] = fma2(wB2[rr][p], hv[p], acc[rr]);
            }
            // finish h2 poll (dependent chain)
            while (!(d0 && d1)) {
                if (!d0) { w0 = ldp(q0); d0 = (ptag(w0) == n2); }
                if (!d1) { w1 = ldp(q1); d1 = (ptag(w1) == n2); }
            }
            sh2[tid]       = pval(w0);
            sh2[tid + 256] = pval(w1);
            __syncthreads();

            // ---- phase 3: Whh2*h2 half + reduce + distributed activation ----
            {
                u64 hv[8];
                const u64* s2 = (const u64*)sh2;
                #pragma unroll
                for (int p = 0; p < 8; ++p) hv[p] = s2[lane + 32 * p];
                float sArr[4];
                #pragma unroll
                for (int rr = 0; rr < 4; ++rr) {
                    #pragma unroll
                    for (int p = 0; p < 8; ++p) acc[rr] = fma2(wB2[rr][8 + p], hv[p], acc[rr]);
                    float a = hsum2(acc[rr]);
                    #pragma unroll
                    for (int o = 16; o; o >>= 1) a += __shfl_xor_sync(0xffffffffu, a, o);
                    sArr[rr] = a;
                }
                float mine = sArr[0];
                mine = (lane == 1) ? sArr[1] : mine;
                mine = (lane == 2) ? sArr[2] : mine;
                mine = (lane == 3) ? sArr[3] : mine;
                if (lane < 4) {
                    int r = wid * 4 + lane;
                    float v = mine + sb[r];
                    sg[r] = ((r >> 3) == 2) ? tanhff(v) : sigf(v);
                }
            }
            __syncthreads();

            // ---- phase 4: warp0 cell update + batched publish (h2 + o) ----
            if (wid == 0) {
                float a = sg[lane];   // activated gate value for row=lane
                int u = lane & 7;
                float i_ = __shfl_sync(0xffffffffu, a, u);
                float f_ = __shfl_sync(0xffffffffu, a, u + 8);
                float g_ = __shfl_sync(0xffffffffu, a, u + 16);
                float o_ = __shfl_sync(0xffffffffu, a, u + 24);
                float p = 0.f;
                if (lane < 8) {
                    c2 = f_ * c2 + i_ * g_;
                    float hh = o_ * tanhff(c2);
                    stp(&g_h2p[(k + 1) & (R2 - 1)][bB + lane], mkpair(hh, n1));
                    p = swlin[lane] * hh;
                }
                if (k >= T - 1) {
                    p += __shfl_xor_sync(0xffffffffu, p, 4);
                    p += __shfl_xor_sync(0xffffffffu, p, 2);
                    p += __shfl_xor_sync(0xffffffffu, p, 1);
                    if (lane == 0)
                        stp(&g_op[(k + 1) & (RO - 1)][jB], mkpair(p, n1));
                }
            }
        }
    }
}

extern "C" void kernel_launch(void* const* d_in, const int* in_sizes, int n_in,
                              void* d_out, int out_size) {
    int off = (n_in >= 12 && in_sizes[1] == 1) ? 2 : 1;

    const float* input = (const float*)d_in[0];
    const float* Wih1  = (const float*)d_in[off + 0];
    const float* Whh1  = (const float*)d_in[off + 1];
    const float* bih1  = (const float*)d_in[off + 2];
    const float* bhh1  = (const float*)d_in[off + 3];
    const float* Wih2  = (const float*)d_in[off + 4];
    const float* Whh2  = (const float*)d_in[off + 5];
    const float* bih2  = (const float*)d_in[off + 6];
    const float* bhh2  = (const float*)d_in[off + 7];
    const float* Wlin  = (const float*)d_in[off + 8];
    const float* blin  = (const float*)d_in[off + 9];

    const int B = 256;
    const int T = in_sizes[0] / B;
    const int pred_len = out_size;

    init_state_kernel<<<1, NTHR>>>();
    lstm_da2_kernel<<<NBLK, NTHR>>>(
        input, Wih1, Whh1, bih1, bhh1, Wih2, Whh2, bih2, bhh2, Wlin, blin,
        (float*)d_out, T, pred_len, B);
}